// round 2
// baseline (speedup 1.0000x reference)
#include <cuda_runtime.h>
#include <cstdint>
#include <cstddef>

#define DEVFN __device__ __forceinline__

// ---------------- static device scratch (no cudaMalloc allowed) -------------
__device__ float g_xproj[16 * 1024 * 1024]; // [bt][1024] gate pre-activations (reused for both layers)
__device__ float g_h0[16 * 1024 * 256];     // layer-0 hidden states
__device__ float g_h1[16 * 1024 * 256];     // layer-1 hidden states

// ---------------- helpers ----------------------------------------------------
DEVFN uint32_t smem_u32(const void* p) {
    uint32_t a;
    asm("{ .reg .u64 t; cvta.to.shared.u64 t, %1; cvt.u32.u64 %0, t; }" : "=r"(a) : "l"(p));
    return a;
}
DEVFN float frcp_(float x) { float r; asm("rcp.approx.f32 %0, %1;" : "=f"(r) : "f"(x)); return r; }
DEVFN float fexp2_(float x) { float r; asm("ex2.approx.f32 %0, %1;" : "=f"(r) : "f"(x)); return r; }
DEVFN float sigm_(float x) { return frcp_(1.0f + fexp2_(-1.4426950408889634f * x)); }
DEVFN float tanh_(float x) { return 1.0f - 2.0f * frcp_(1.0f + fexp2_(2.8853900817779268f * x)); }
DEVFN void cluster_sync_() {
    asm volatile("barrier.cluster.arrive.aligned;\n\tbarrier.cluster.wait.aligned;\n" ::: "memory");
}
DEVFN void remote_st_f32(uint32_t addr, float v, uint32_t peer) {
    asm volatile(
        "{\n\t.reg .b32 ra;\n\t"
        "mapa.shared::cluster.u32 ra, %0, %2;\n\t"
        "st.shared::cluster.f32 [ra], %1;\n\t}"
        :: "r"(addr), "f"(v), "r"(peer) : "memory");
}

// ============================================================================
// GEMM: C[m][n] = sum_k A[m][k]*B[n][k] + bias1[n] + bias2[n]
// A: (16384, K), B: (1024, K), C: g_xproj (16384, 1024). K in {32, 256}.
// 64x64 tile, 256 threads, 4x4 microtile, K-panels of 32, transposed smem tiles.
// ============================================================================
__global__ void __launch_bounds__(256, 4)
gemm_xproj(const float* __restrict__ A, const float* __restrict__ B,
           const float* __restrict__ bias1, const float* __restrict__ bias2,
           float* __restrict__ C, int K)
{
    __shared__ __align__(16) float As[32][68];
    __shared__ __align__(16) float Bs[32][68];

    const int tid = threadIdx.x;
    const int tx = tid & 15, ty = tid >> 4;
    const int m0 = blockIdx.y * 64, n0 = blockIdx.x * 64;
    const int lr = tid >> 2;           // 0..63 tile row for loads
    const int lcb = (tid & 3) * 4;     // k base (float4)

    float acc[4][4] = {};

    for (int kk = 0; kk < K; kk += 32) {
#pragma unroll
        for (int it = 0; it < 2; it++) {
            int k0 = lcb + it * 16;
            float4 a = *(const float4*)(A + (size_t)(m0 + lr) * K + kk + k0);
            As[k0 + 0][lr] = a.x; As[k0 + 1][lr] = a.y;
            As[k0 + 2][lr] = a.z; As[k0 + 3][lr] = a.w;
            float4 bb = *(const float4*)(B + (size_t)(n0 + lr) * K + kk + k0);
            Bs[k0 + 0][lr] = bb.x; Bs[k0 + 1][lr] = bb.y;
            Bs[k0 + 2][lr] = bb.z; Bs[k0 + 3][lr] = bb.w;
        }
        __syncthreads();
#pragma unroll
        for (int k = 0; k < 32; k++) {
            float4 av = *(const float4*)&As[k][ty * 4];
            float4 bv = *(const float4*)&Bs[k][tx * 4];
            float am[4] = {av.x, av.y, av.z, av.w};
            float bn[4] = {bv.x, bv.y, bv.z, bv.w};
#pragma unroll
            for (int i = 0; i < 4; i++)
#pragma unroll
                for (int jn = 0; jn < 4; jn++)
                    acc[i][jn] = fmaf(am[i], bn[jn], acc[i][jn]);
        }
        __syncthreads();
    }
    float4 b1 = *(const float4*)(bias1 + n0 + tx * 4);
    float4 b2 = *(const float4*)(bias2 + n0 + tx * 4);
    float bad[4] = {b1.x + b2.x, b1.y + b2.y, b1.z + b2.z, b1.w + b2.w};
#pragma unroll
    for (int i = 0; i < 4; i++) {
        float4 o;
        o.x = acc[i][0] + bad[0]; o.y = acc[i][1] + bad[1];
        o.z = acc[i][2] + bad[2]; o.w = acc[i][3] + bad[3];
        *(float4*)(C + (size_t)(m0 + ty * 4 + i) * 1024 + n0 + tx * 4) = o;
    }
}

// ============================================================================
// LSTM recurrence. 8-CTA cluster per batch element; grid = 128 CTAs x 512 thr.
// CTA rank r owns h indices [32r, 32r+32). Thread (j=tid>>4, p=tid&15) holds
// W_hh[g*256 + 32r + j][16p .. 16p+16) for all 4 gates (64 floats in regs).
// h double-buffered in SMEM (16 chunks of 16 floats padded to 20), broadcast
// each step to all 8 CTAs via st.shared::cluster; one cluster.sync per step.
// ============================================================================
__global__ void __cluster_dims__(8, 1, 1) __launch_bounds__(512, 1)
lstm_kernel(const float* __restrict__ Whh, const float* __restrict__ xproj,
            float* __restrict__ hout)
{
    __shared__ __align__(16) float hbuf[2][320];
    __shared__ __align__(16) float garr[32][4];

    const int tid = threadIdx.x;
    const int p = tid & 15;
    const int j = tid >> 4;
    const int wid = tid >> 5;
    const int lane = tid & 31;
    uint32_t rank;
    asm("mov.u32 %0, %%cluster_ctarank;" : "=r"(rank));
    const int b = blockIdx.x >> 3;
    const int base = (int)rank * 32;

    // W in registers: 4 gates x 16 floats
    float4 W[4][4];
#pragma unroll
    for (int g = 0; g < 4; g++) {
        const float4* wp = (const float4*)(Whh + (size_t)(g * 256 + base + j) * 256 + p * 16);
#pragma unroll
        for (int i = 0; i < 4; i++) W[g][i] = wp[i];
    }

    for (int i = tid; i < 640; i += 512) (&hbuf[0][0])[i] = 0.0f;
    __syncthreads();
    cluster_sync_();

    float c = 0.0f;
    const float* xpb = xproj + (size_t)b * 1024 * 1024;

#pragma unroll 1
    for (int t = 0; t < 1024; t++) {
        float xp0, xp1, xp2, xp3;
        if (wid == 0) {  // prefetch this step's x_proj contributions (L2)
            const float* xr = xpb + (size_t)t * 1024 + base + lane;
            xp0 = xr[0]; xp1 = xr[256]; xp2 = xr[512]; xp3 = xr[768];
        }
        const float* hbp = hbuf[t & 1] + p * 20;
        float4 h0 = ((const float4*)hbp)[0];
        float4 h1 = ((const float4*)hbp)[1];
        float4 h2 = ((const float4*)hbp)[2];
        float4 h3 = ((const float4*)hbp)[3];
        float s0 = 0.f, s1 = 0.f, s2 = 0.f, s3 = 0.f;
#define D4(S, WV, HV) S = fmaf((WV).x,(HV).x, fmaf((WV).y,(HV).y, fmaf((WV).z,(HV).z, fmaf((WV).w,(HV).w,(S)))))
        D4(s0, W[0][0], h0); D4(s0, W[0][1], h1); D4(s0, W[0][2], h2); D4(s0, W[0][3], h3);
        D4(s1, W[1][0], h0); D4(s1, W[1][1], h1); D4(s1, W[1][2], h2); D4(s1, W[1][3], h3);
        D4(s2, W[2][0], h0); D4(s2, W[2][1], h1); D4(s2, W[2][2], h2); D4(s2, W[2][3], h3);
        D4(s3, W[3][0], h0); D4(s3, W[3][1], h1); D4(s3, W[3][2], h2); D4(s3, W[3][3], h3);
#undef D4
#pragma unroll
        for (int m = 1; m < 16; m <<= 1) {
            s0 += __shfl_xor_sync(0xffffffffu, s0, m);
            s1 += __shfl_xor_sync(0xffffffffu, s1, m);
            s2 += __shfl_xor_sync(0xffffffffu, s2, m);
            s3 += __shfl_xor_sync(0xffffffffu, s3, m);
        }
        if (p == 0) { garr[j][0] = s0; garr[j][1] = s1; garr[j][2] = s2; garr[j][3] = s3; }
        __syncthreads();
        if (wid == 0) {  // one dense warp does all 32 activations + broadcast
            float4 gv = *(const float4*)garr[lane];
            float iv = sigm_(gv.x + xp0);
            float fv = sigm_(gv.y + xp1);
            float gg = tanh_(gv.z + xp2);
            float ov = sigm_(gv.w + xp3);
            c = fmaf(fv, c, iv * gg);
            float hval = ov * tanh_(c);
            hout[(size_t)(b * 1024 + t) * 256 + base + lane] = hval;
            int gidx = base + lane;
            uint32_t addr = smem_u32(&hbuf[(t & 1) ^ 1][(gidx >> 4) * 20 + (gidx & 15)]);
#pragma unroll
            for (int rr = 0; rr < 8; rr++) remote_st_f32(addr, hval, (uint32_t)rr);
        }
        cluster_sync_();  // release DSMEM stores + covers garr/hbuf hazards
    }
}

// ============================================================================
// Attention (last timestep only, algebraically reduced) + output heads.
// One CTA per batch element; warp w handles head w (NH=8).
// ============================================================================
#define ATTN_SMEM_FLOATS 17416
#define ATTN_SMEM_BYTES (ATTN_SMEM_FLOATS * 4)

__global__ void __launch_bounds__(256, 1)
attn_kernel(const float* __restrict__ h1all,
            const float* __restrict__ Wq, const float* __restrict__ bq,
            const float* __restrict__ Wk, const float* __restrict__ bk,
            const float* __restrict__ Wv, const float* __restrict__ bv,
            const float* __restrict__ Wo, const float* __restrict__ bo,
            const float* __restrict__ Wm, const float* __restrict__ bm,
            const float* __restrict__ Wvar, const float* __restrict__ bvar,
            float* __restrict__ out)
{
    extern __shared__ float sm[];
    float* tile   = sm;           // 16 x 256 = 4096
    float* scores = sm + 4096;    // 8 x 1024
    float* u      = sm + 12288;   // 8 x 256
    float* hb     = sm + 14336;   // 8 x 256
    float* qv     = sm + 16384;   // 256
    float* h2last = sm + 16640;   // 256
    float* attnv  = sm + 16896;   // 256
    float* ctx    = sm + 17152;   // 256
    float* qb     = sm + 17408;   // 8

    const int b = blockIdx.x;
    const int tid = threadIdx.x;
    const int w = tid >> 5, lane = tid & 31;
    const float* hbase = h1all + (size_t)b * 1024 * 256;

    h2last[tid] = hbase[1023 * 256 + tid];
    __syncthreads();

    // q = h_last @ Wq^T + bq
    {
        float acc = bq[tid];
        const float* wr = Wq + (size_t)tid * 256;
#pragma unroll 8
        for (int d = 0; d < 256; d++) acc = fmaf(wr[d], h2last[d], acc);
        qv[tid] = acc;
    }
    __syncthreads();

    // u[h] = Wk_h^T q_h ; qb[h] = q_h . bk_h
#pragma unroll 1
    for (int i = 0; i < 8; i++) {
        int flat = tid + (i << 8);
        int hh = flat >> 8, d = flat & 255;
        float acc = 0.0f;
        const float* basep = Wk + (size_t)hh * 32 * 256 + d;
#pragma unroll
        for (int e = 0; e < 32; e++) acc = fmaf(basep[(size_t)e * 256], qv[(hh << 5) + e], acc);
        u[hh * 256 + d] = acc;
    }
    if (tid < 8) {
        float a = 0.0f;
        for (int e = 0; e < 32; e++) a = fmaf(qv[tid * 32 + e], bk[tid * 32 + e], a);
        qb[tid] = a;
    }
    __syncthreads();

    const float scale = 0.17677669529663687f;         // 1/sqrt(32)
    const float L2D   = -0.07400058144377693f;        // log2(0.95)
    const float LOG2E = 1.4426950408889634f;
    float mmax = -1e30f;

    // pass 1: scores
#pragma unroll 1
    for (int tt = 0; tt < 64; tt++) {
        {
            int tl = tid >> 4, d0 = (tid & 15) * 16;
            const float4* src = (const float4*)(hbase + (size_t)(tt * 16 + tl) * 256 + d0);
            float4* dst = (float4*)(tile + tl * 256 + d0);
            dst[0] = src[0]; dst[1] = src[1]; dst[2] = src[2]; dst[3] = src[3];
        }
        __syncthreads();
#pragma unroll 1
        for (int tl = 0; tl < 16; tl++) {
            int t = tt * 16 + tl;
            float part = 0.0f;
            const float* tr = tile + tl * 256 + lane * 8;
            const float* ur = u + w * 256 + lane * 8;
#pragma unroll
            for (int i = 0; i < 8; i++) part = fmaf(ur[i], tr[i], part);
#pragma unroll
            for (int m = 16; m > 0; m >>= 1) part += __shfl_xor_sync(0xffffffffu, part, m);
            float s = (part + qb[w]) * scale * fexp2_((float)(1023 - t) * L2D);
            if (lane == 0) scores[w * 1024 + t] = s;
            mmax = fmaxf(mmax, s);
        }
        __syncthreads();
    }

    // softmax normalizer
    float Z = 0.0f;
    for (int t = lane; t < 1024; t += 32) Z += fexp2_(LOG2E * (scores[w * 1024 + t] - mmax));
#pragma unroll
    for (int m = 16; m > 0; m >>= 1) Z += __shfl_xor_sync(0xffffffffu, Z, m);
    float invZ = 1.0f / Z;

    // pass 2: hbar = sum_t p_t * h_t
    float hbar[8] = {0, 0, 0, 0, 0, 0, 0, 0};
#pragma unroll 1
    for (int tt = 0; tt < 64; tt++) {
        {
            int tl = tid >> 4, d0 = (tid & 15) * 16;
            const float4* src = (const float4*)(hbase + (size_t)(tt * 16 + tl) * 256 + d0);
            float4* dst = (float4*)(tile + tl * 256 + d0);
            dst[0] = src[0]; dst[1] = src[1]; dst[2] = src[2]; dst[3] = src[3];
        }
        __syncthreads();
#pragma unroll 1
        for (int tl = 0; tl < 16; tl++) {
            int t = tt * 16 + tl;
            float pr = fexp2_(LOG2E * (scores[w * 1024 + t] - mmax)) * invZ;
            const float* tr = tile + tl * 256 + lane * 8;
#pragma unroll
            for (int i = 0; i < 8; i++) hbar[i] = fmaf(pr, tr[i], hbar[i]);
        }
        __syncthreads();
    }
#pragma unroll
    for (int i = 0; i < 8; i++) hb[w * 256 + lane * 8 + i] = hbar[i];
    __syncthreads();

    // attnv[e] = Wv[e] . hbar(head of e) + bv[e]
    {
        int hh = tid >> 5;
        float acc = bv[tid];
        const float* wr = Wv + (size_t)tid * 256;
        const float* hr = hb + hh * 256;
#pragma unroll 8
        for (int d = 0; d < 256; d++) acc = fmaf(wr[d], hr[d], acc);
        attnv[tid] = acc;
    }
    __syncthreads();
    // ctx = attnv @ Wo^T + bo
    {
        float acc = bo[tid];
        const float* wr = Wo + (size_t)tid * 256;
#pragma unroll 8
        for (int d = 0; d < 256; d++) acc = fmaf(wr[d], attnv[d], acc);
        ctx[tid] = acc;
    }
    __syncthreads();
    // heads
    if (tid < 5) {
        float acc = bm[tid];
        const float* wr = Wm + (size_t)tid * 256;
#pragma unroll 8
        for (int d = 0; d < 256; d++) acc = fmaf(wr[d], ctx[d], acc);
        out[b * 5 + tid] = acc;
    } else if (tid >= 32 && tid < 37) {
        int jj = tid - 32;
        float acc = bvar[jj];
        const float* wr = Wvar + (size_t)jj * 256;
#pragma unroll 8
        for (int d = 0; d < 256; d++) acc = fmaf(wr[d], ctx[d], acc);
        out[80 + b * 5 + jj] = acc;
    }
}

// ============================================================================
extern "C" void kernel_launch(void* const* d_in, const int* in_sizes, int n_in,
                              void* d_out, int out_size)
{
    (void)in_sizes; (void)n_in; (void)out_size;
    const float* x    = (const float*)d_in[0];
    const float* Wih0 = (const float*)d_in[1];
    const float* Whh0 = (const float*)d_in[2];
    const float* bih0 = (const float*)d_in[3];
    const float* bhh0 = (const float*)d_in[4];
    const float* Wih1 = (const float*)d_in[5];
    const float* Whh1 = (const float*)d_in[6];
    const float* bih1 = (const float*)d_in[7];
    const float* bhh1 = (const float*)d_in[8];
    const float* Wq   = (const float*)d_in[9];
    const float* bq   = (const float*)d_in[10];
    const float* Wk   = (const float*)d_in[11];
    const float* bk   = (const float*)d_in[12];
    const float* Wv   = (const float*)d_in[13];
    const float* bv   = (const float*)d_in[14];
    const float* Wo   = (const float*)d_in[15];
    const float* bo   = (const float*)d_in[16];
    const float* Wm   = (const float*)d_in[17];
    const float* bm   = (const float*)d_in[18];
    const float* Wvar = (const float*)d_in[19];
    const float* bvar = (const float*)d_in[20];
    float* out = (float*)d_out;

    float *xp, *h0p, *h1p;
    cudaGetSymbolAddress((void**)&xp,  g_xproj);
    cudaGetSymbolAddress((void**)&h0p, g_h0);
    cudaGetSymbolAddress((void**)&h1p, g_h1);
    cudaFuncSetAttribute(attn_kernel, cudaFuncAttributeMaxDynamicSharedMemorySize, ATTN_SMEM_BYTES);

    // x_proj for layer 0 (K=32), LSTM 0, x_proj for layer 1 (K=256), LSTM 1, attention
    gemm_xproj<<<dim3(16, 256), 256>>>(x,   Wih0, bih0, bhh0, xp, 32);
    lstm_kernel<<<128, 512>>>(Whh0, xp, h0p);
    gemm_xproj<<<dim3(16, 256), 256>>>(h0p, Wih1, bih1, bhh1, xp, 256);
    lstm_kernel<<<128, 512>>>(Whh1, xp, h1p);
    attn_kernel<<<16, 256, ATTN_SMEM_BYTES>>>(h1p, Wq, bq, Wk, bk, Wv, bv, Wo, bo,
                                              Wm, bm, Wvar, bvar, out);
}

// round 4
// speedup vs baseline: 1.3658x; 1.3658x over previous
#include <cuda_runtime.h>
#include <cstdint>
#include <cstddef>

#define DEVFN __device__ __forceinline__
typedef unsigned long long u64t;

// ---------------- static device scratch (no cudaMalloc allowed) -------------
__device__ float g_xproj[16 * 1024 * 1024]; // [bt][1024] gate pre-activations (reused for both layers)
__device__ float g_h0[16 * 1024 * 256];     // layer-0 hidden states
__device__ float g_h1[16 * 1024 * 256];     // layer-1 hidden states

// ---------------- helpers ----------------------------------------------------
DEVFN uint32_t smem_u32(const void* p) {
    uint32_t a;
    asm("{ .reg .u64 t; cvta.to.shared.u64 t, %1; cvt.u32.u64 %0, t; }" : "=r"(a) : "l"(p));
    return a;
}
DEVFN float frcp_(float x) { float r; asm("rcp.approx.f32 %0, %1;" : "=f"(r) : "f"(x)); return r; }
DEVFN float fexp2_(float x) { float r; asm("ex2.approx.f32 %0, %1;" : "=f"(r) : "f"(x)); return r; }
DEVFN float sigm_(float x) { return frcp_(1.0f + fexp2_(-1.4426950408889634f * x)); }
DEVFN float tanh_(float x) { return 1.0f - 2.0f * frcp_(1.0f + fexp2_(2.8853900817779268f * x)); }
DEVFN void cluster_sync_() {
    asm volatile("barrier.cluster.arrive.aligned;\n\tbarrier.cluster.wait.aligned;\n" ::: "memory");
}
DEVFN u64t ffma2_(u64t a, u64t b, u64t c) {
    u64t d;
    asm("fma.rn.f32x2 %0, %1, %2, %3;" : "=l"(d) : "l"(a), "l"(b), "l"(c));
    return d;
}
DEVFN float pairsum_(u64t s) {
    return __uint_as_float((uint32_t)s) + __uint_as_float((uint32_t)(s >> 32));
}
DEVFN uint32_t mapa_(uint32_t addr, uint32_t peer) {
    uint32_t r;
    asm("mapa.shared::cluster.u32 %0, %1, %2;" : "=r"(r) : "r"(addr), "r"(peer));
    return r;
}
DEVFN void mbar_init_(uint32_t a, uint32_t cnt) {
    asm volatile("mbarrier.init.shared.b64 [%0], %1;" :: "r"(a), "r"(cnt) : "memory");
}
DEVFN void mbar_expect_(uint32_t a, uint32_t bytes) {
    asm volatile("mbarrier.arrive.expect_tx.shared.b64 _, [%0], %1;" :: "r"(a), "r"(bytes) : "memory");
}
DEVFN void mbar_wait_(uint32_t a, uint32_t par) {
    asm volatile(
        "{\n\t.reg .pred P;\n\t"
        "W%=:\n\t"
        "mbarrier.try_wait.parity.acquire.cluster.shared::cta.b64 P, [%0], %1, 0x989680;\n\t"
        "@!P bra W%=;\n\t}"
        :: "r"(a), "r"(par) : "memory");
}
// remote SMEM store with tx-byte completion on the remote CTA's mbarrier
// (canonical PTX form; no .weak qualifier)
DEVFN void st_async_f32_(uint32_t raddr, float v, uint32_t rmbar) {
    asm volatile(
        "st.async.shared::cluster.mbarrier::complete_tx::bytes.b32 [%0], %1, [%2];"
        :: "r"(raddr), "r"(__float_as_uint(v)), "r"(rmbar) : "memory");
}

// ============================================================================
// GEMM: C[m][n] = sum_k A[m][k]*B[n][k] + bias1[n] + bias2[n]
// A: (16384, K), B: (1024, K), C: g_xproj (16384, 1024). K in {32, 256}.
// ============================================================================
__global__ void __launch_bounds__(256, 4)
gemm_xproj(const float* __restrict__ A, const float* __restrict__ B,
           const float* __restrict__ bias1, const float* __restrict__ bias2,
           float* __restrict__ C, int K)
{
    __shared__ __align__(16) float As[32][68];
    __shared__ __align__(16) float Bs[32][68];

    const int tid = threadIdx.x;
    const int tx = tid & 15, ty = tid >> 4;
    const int m0 = blockIdx.y * 64, n0 = blockIdx.x * 64;
    const int lr = tid >> 2;
    const int lcb = (tid & 3) * 4;

    float acc[4][4] = {};

    for (int kk = 0; kk < K; kk += 32) {
#pragma unroll
        for (int it = 0; it < 2; it++) {
            int k0 = lcb + it * 16;
            float4 a = *(const float4*)(A + (size_t)(m0 + lr) * K + kk + k0);
            As[k0 + 0][lr] = a.x; As[k0 + 1][lr] = a.y;
            As[k0 + 2][lr] = a.z; As[k0 + 3][lr] = a.w;
            float4 bb = *(const float4*)(B + (size_t)(n0 + lr) * K + kk + k0);
            Bs[k0 + 0][lr] = bb.x; Bs[k0 + 1][lr] = bb.y;
            Bs[k0 + 2][lr] = bb.z; Bs[k0 + 3][lr] = bb.w;
        }
        __syncthreads();
#pragma unroll
        for (int k = 0; k < 32; k++) {
            float4 av = *(const float4*)&As[k][ty * 4];
            float4 bv = *(const float4*)&Bs[k][tx * 4];
            float am[4] = {av.x, av.y, av.z, av.w};
            float bn[4] = {bv.x, bv.y, bv.z, bv.w};
#pragma unroll
            for (int i = 0; i < 4; i++)
#pragma unroll
                for (int jn = 0; jn < 4; jn++)
                    acc[i][jn] = fmaf(am[i], bn[jn], acc[i][jn]);
        }
        __syncthreads();
    }
    float4 b1 = *(const float4*)(bias1 + n0 + tx * 4);
    float4 b2 = *(const float4*)(bias2 + n0 + tx * 4);
    float bad[4] = {b1.x + b2.x, b1.y + b2.y, b1.z + b2.z, b1.w + b2.w};
#pragma unroll
    for (int i = 0; i < 4; i++) {
        float4 o;
        o.x = acc[i][0] + bad[0]; o.y = acc[i][1] + bad[1];
        o.z = acc[i][2] + bad[2]; o.w = acc[i][3] + bad[3];
        *(float4*)(C + (size_t)(m0 + ty * 4 + i) * 1024 + n0 + tx * 4) = o;
    }
}

// ============================================================================
// LSTM recurrence. 8-CTA cluster per batch element; grid = 128 CTAs x 512 thr.
// CTA rank r owns h indices [32r, 32r+32). Thread (j=tid>>4, p=tid&15) holds
// W_hh[g*256 + 32r + j][16p..16p+16) for all 4 gates, as packed f32x2 pairs.
// Handoff per step: warp 0 computes the 32 h-values and pushes them into all
// 8 CTAs' double-buffered SMEM h via st.async + tx-byte mbarrier completion.
// Two mbarriers (one per buffer parity) give the required slack-2.
// ============================================================================
__global__ void __cluster_dims__(8, 1, 1) __launch_bounds__(512, 1)
lstm_kernel(const float* __restrict__ Whh, const float* __restrict__ xproj,
            float* __restrict__ hout)
{
    __shared__ __align__(16) float hbuf[2][320];          // 16 chunks of 16 floats padded to 20
    __shared__ __align__(16) float garr[32][4];
    __shared__ __align__(8)  unsigned long long mbar[2];

    const int tid = threadIdx.x;
    const int p = tid & 15;
    const int j = tid >> 4;
    const int wid = tid >> 5;
    const int lane = tid & 31;
    uint32_t rank;
    asm("mov.u32 %0, %%cluster_ctarank;" : "=r"(rank));
    const int b = blockIdx.x >> 3;
    const int base = (int)rank * 32;

    // W in registers as packed f32x2: 4 gates x 4 ulonglong2 (16 floats each)
    ulonglong2 W[4][4];
#pragma unroll
    for (int g = 0; g < 4; g++) {
        const ulonglong2* wp = (const ulonglong2*)(Whh + (size_t)(g * 256 + base + j) * 256 + p * 16);
#pragma unroll
        for (int i = 0; i < 4; i++) W[g][i] = wp[i];
    }

    if (tid < 320) hbuf[0][tid] = 0.0f;
    const uint32_t mb0 = smem_u32(&mbar[0]);
    const uint32_t mb1 = smem_u32(&mbar[1]);
    if (tid == 0) { mbar_init_(mb0, 1); mbar_init_(mb1, 1); }
    __syncthreads();
    cluster_sync_();   // peers' mbarriers + zeroed hbuf visible before any st.async

    // warp 0: precompute remote addresses (own slot in each peer's hbuf[0], and mbarriers)
    uint32_t rdata[8], rmb0[8], rmb1[8];
    if (wid == 0) {
        int gidx = base + lane;
        uint32_t slot = smem_u32(&hbuf[0][(gidx >> 4) * 20 + (gidx & 15)]);
#pragma unroll
        for (int r = 0; r < 8; r++) {
            rdata[r] = mapa_(slot, (uint32_t)r);
            rmb0[r] = mapa_(mb0, (uint32_t)r);
            rmb1[r] = mapa_(mb1, (uint32_t)r);
        }
    }

    float c = 0.0f;
    const float* xpb = xproj + (size_t)b * 1024 * 1024;

#pragma unroll 1
    for (int t = 0; t < 1024; t++) {
        float xp0, xp1, xp2, xp3;
        if (wid == 0) {   // issue xproj loads BEFORE the wait: latency fully hidden
            const float* xr = xpb + (size_t)t * 1024 + base + lane;
            xp0 = xr[0]; xp1 = xr[256]; xp2 = xr[512]; xp3 = xr[768];
        }
        if (t > 0) mbar_wait_((t & 1) ? mb0 : mb1, (uint32_t)(((t - 1) >> 1) & 1));
        if (tid == 0) mbar_expect_((t & 1) ? mb1 : mb0, 1024);   // 256 floats arrive this step

        const ulonglong2* hbp = (const ulonglong2*)(hbuf[t & 1] + p * 20);
        ulonglong2 H0 = hbp[0], H1 = hbp[1], H2 = hbp[2], H3 = hbp[3];
        u64t s0 = 0ULL, s1 = 0ULL, s2 = 0ULL, s3 = 0ULL;
#define DP(S, G) \
        S = ffma2_(W[G][0].x, H0.x, S); S = ffma2_(W[G][0].y, H0.y, S); \
        S = ffma2_(W[G][1].x, H1.x, S); S = ffma2_(W[G][1].y, H1.y, S); \
        S = ffma2_(W[G][2].x, H2.x, S); S = ffma2_(W[G][2].y, H2.y, S); \
        S = ffma2_(W[G][3].x, H3.x, S); S = ffma2_(W[G][3].y, H3.y, S);
        DP(s0, 0) DP(s1, 1) DP(s2, 2) DP(s3, 3)
#undef DP
        float f0 = pairsum_(s0), f1 = pairsum_(s1), f2 = pairsum_(s2), f3 = pairsum_(s3);
#pragma unroll
        for (int m = 1; m < 16; m <<= 1) {
            f0 += __shfl_xor_sync(0xffffffffu, f0, m);
            f1 += __shfl_xor_sync(0xffffffffu, f1, m);
            f2 += __shfl_xor_sync(0xffffffffu, f2, m);
            f3 += __shfl_xor_sync(0xffffffffu, f3, m);
        }
        if (p == 0) *(float4*)garr[j] = make_float4(f0, f1, f2, f3);
        __syncthreads();
        if (wid == 0) {   // one dense warp: activations + broadcast via st.async
            float4 gv = *(const float4*)garr[lane];
            float iv = sigm_(gv.x + xp0);
            float fv = sigm_(gv.y + xp1);
            float gg = tanh_(gv.z + xp2);
            float ov = sigm_(gv.w + xp3);
            c = fmaf(fv, c, iv * gg);
            float hval = ov * tanh_(c);
            hout[(size_t)(b * 1024 + t) * 256 + base + lane] = hval;
            uint32_t boff = ((t + 1) & 1) * 1280;          // bytes: next h buffer
            const uint32_t* rmb = (t & 1) ? rmb1 : rmb0;
#pragma unroll
            for (int r = 0; r < 8; r++) st_async_f32_(rdata[r] + boff, hval, rmb[r]);
        }
    }
    cluster_sync_();   // don't exit while peers' st.asyncs may still be in flight
}

// ============================================================================
// Attention (last timestep only, algebraically reduced) + output heads.
// ============================================================================
#define ATTN_SMEM_FLOATS 17416
#define ATTN_SMEM_BYTES (ATTN_SMEM_FLOATS * 4)

__global__ void __launch_bounds__(256, 1)
attn_kernel(const float* __restrict__ h1all,
            const float* __restrict__ Wq, const float* __restrict__ bq,
            const float* __restrict__ Wk, const float* __restrict__ bk,
            const float* __restrict__ Wv, const float* __restrict__ bv,
            const float* __restrict__ Wo, const float* __restrict__ bo,
            const float* __restrict__ Wm, const float* __restrict__ bm,
            const float* __restrict__ Wvar, const float* __restrict__ bvar,
            float* __restrict__ out)
{
    extern __shared__ float sm[];
    float* tile   = sm;           // 16 x 256
    float* scores = sm + 4096;    // 8 x 1024
    float* u      = sm + 12288;   // 8 x 256
    float* hb     = sm + 14336;   // 8 x 256
    float* qv     = sm + 16384;   // 256
    float* h2last = sm + 16640;   // 256
    float* attnv  = sm + 16896;   // 256
    float* ctx    = sm + 17152;   // 256
    float* qb     = sm + 17408;   // 8

    const int b = blockIdx.x;
    const int tid = threadIdx.x;
    const int w = tid >> 5, lane = tid & 31;
    const float* hbase = h1all + (size_t)b * 1024 * 256;

    h2last[tid] = hbase[1023 * 256 + tid];
    __syncthreads();

    {
        float acc = bq[tid];
        const float* wr = Wq + (size_t)tid * 256;
#pragma unroll 8
        for (int d = 0; d < 256; d++) acc = fmaf(wr[d], h2last[d], acc);
        qv[tid] = acc;
    }
    __syncthreads();

#pragma unroll 1
    for (int i = 0; i < 8; i++) {
        int flat = tid + (i << 8);
        int hh = flat >> 8, d = flat & 255;
        float acc = 0.0f;
        const float* basep = Wk + (size_t)hh * 32 * 256 + d;
#pragma unroll
        for (int e = 0; e < 32; e++) acc = fmaf(basep[(size_t)e * 256], qv[(hh << 5) + e], acc);
        u[hh * 256 + d] = acc;
    }
    if (tid < 8) {
        float a = 0.0f;
        for (int e = 0; e < 32; e++) a = fmaf(qv[tid * 32 + e], bk[tid * 32 + e], a);
        qb[tid] = a;
    }
    __syncthreads();

    const float scale = 0.17677669529663687f;   // 1/sqrt(32)
    const float L2D   = -0.07400058144377693f;  // log2(0.95)
    const float LOG2E = 1.4426950408889634f;
    float mmax = -1e30f;

#pragma unroll 1
    for (int tt = 0; tt < 64; tt++) {
        {
            int tl = tid >> 4, d0 = (tid & 15) * 16;
            const float4* src = (const float4*)(hbase + (size_t)(tt * 16 + tl) * 256 + d0);
            float4* dst = (float4*)(tile + tl * 256 + d0);
            dst[0] = src[0]; dst[1] = src[1]; dst[2] = src[2]; dst[3] = src[3];
        }
        __syncthreads();
#pragma unroll 1
        for (int tl = 0; tl < 16; tl++) {
            int t = tt * 16 + tl;
            float part = 0.0f;
            const float* tr = tile + tl * 256 + lane * 8;
            const float* ur = u + w * 256 + lane * 8;
#pragma unroll
            for (int i = 0; i < 8; i++) part = fmaf(ur[i], tr[i], part);
#pragma unroll
            for (int m = 16; m > 0; m >>= 1) part += __shfl_xor_sync(0xffffffffu, part, m);
            float s = (part + qb[w]) * scale * fexp2_((float)(1023 - t) * L2D);
            if (lane == 0) scores[w * 1024 + t] = s;
            mmax = fmaxf(mmax, s);
        }
        __syncthreads();
    }

    float Z = 0.0f;
    for (int t = lane; t < 1024; t += 32) Z += fexp2_(LOG2E * (scores[w * 1024 + t] - mmax));
#pragma unroll
    for (int m = 16; m > 0; m >>= 1) Z += __shfl_xor_sync(0xffffffffu, Z, m);
    float invZ = 1.0f / Z;

    float hbar[8] = {0, 0, 0, 0, 0, 0, 0, 0};
#pragma unroll 1
    for (int tt = 0; tt < 64; tt++) {
        {
            int tl = tid >> 4, d0 = (tid & 15) * 16;
            const float4* src = (const float4*)(hbase + (size_t)(tt * 16 + tl) * 256 + d0);
            float4* dst = (float4*)(tile + tl * 256 + d0);
            dst[0] = src[0]; dst[1] = src[1]; dst[2] = src[2]; dst[3] = src[3];
        }
        __syncthreads();
#pragma unroll 1
        for (int tl = 0; tl < 16; tl++) {
            int t = tt * 16 + tl;
            float pr = fexp2_(LOG2E * (scores[w * 1024 + t] - mmax)) * invZ;
            const float* tr = tile + tl * 256 + lane * 8;
#pragma unroll
            for (int i = 0; i < 8; i++) hbar[i] = fmaf(pr, tr[i], hbar[i]);
        }
        __syncthreads();
    }
#pragma unroll
    for (int i = 0; i < 8; i++) hb[w * 256 + lane * 8 + i] = hbar[i];
    __syncthreads();

    {
        int hh = tid >> 5;
        float acc = bv[tid];
        const float* wr = Wv + (size_t)tid * 256;
        const float* hr = hb + hh * 256;
#pragma unroll 8
        for (int d = 0; d < 256; d++) acc = fmaf(wr[d], hr[d], acc);
        attnv[tid] = acc;
    }
    __syncthreads();
    {
        float acc = bo[tid];
        const float* wr = Wo + (size_t)tid * 256;
#pragma unroll 8
        for (int d = 0; d < 256; d++) acc = fmaf(wr[d], attnv[d], acc);
        ctx[tid] = acc;
    }
    __syncthreads();
    if (tid < 5) {
        float acc = bm[tid];
        const float* wr = Wm + (size_t)tid * 256;
#pragma unroll 8
        for (int d = 0; d < 256; d++) acc = fmaf(wr[d], ctx[d], acc);
        out[b * 5 + tid] = acc;
    } else if (tid >= 32 && tid < 37) {
        int jj = tid - 32;
        float acc = bvar[jj];
        const float* wr = Wvar + (size_t)jj * 256;
#pragma unroll 8
        for (int d = 0; d < 256; d++) acc = fmaf(wr[d], ctx[d], acc);
        out[80 + b * 5 + jj] = acc;
    }
}

// ============================================================================
extern "C" void kernel_launch(void* const* d_in, const int* in_sizes, int n_in,
                              void* d_out, int out_size)
{
    (void)in_sizes; (void)n_in; (void)out_size;
    const float* x    = (const float*)d_in[0];
    const float* Wih0 = (const float*)d_in[1];
    const float* Whh0 = (const float*)d_in[2];
    const float* bih0 = (const float*)d_in[3];
    const float* bhh0 = (const float*)d_in[4];
    const float* Wih1 = (const float*)d_in[5];
    const float* Whh1 = (const float*)d_in[6];
    const float* bih1 = (const float*)d_in[7];
    const float* bhh1 = (const float*)d_in[8];
    const float* Wq   = (const float*)d_in[9];
    const float* bq   = (const float*)d_in[10];
    const float* Wk   = (const float*)d_in[11];
    const float* bk   = (const float*)d_in[12];
    const float* Wv   = (const float*)d_in[13];
    const float* bv   = (const float*)d_in[14];
    const float* Wo   = (const float*)d_in[15];
    const float* bo   = (const float*)d_in[16];
    const float* Wm   = (const float*)d_in[17];
    const float* bm   = (const float*)d_in[18];
    const float* Wvar = (const float*)d_in[19];
    const float* bvar = (const float*)d_in[20];
    float* out = (float*)d_out;

    float *xp, *h0p, *h1p;
    cudaGetSymbolAddress((void**)&xp,  g_xproj);
    cudaGetSymbolAddress((void**)&h0p, g_h0);
    cudaGetSymbolAddress((void**)&h1p, g_h1);
    cudaFuncSetAttribute(attn_kernel, cudaFuncAttributeMaxDynamicSharedMemorySize, ATTN_SMEM_BYTES);

    gemm_xproj<<<dim3(16, 256), 256>>>(x,   Wih0, bih0, bhh0, xp, 32);
    lstm_kernel<<<128, 512>>>(Whh0, xp, h0p);
    gemm_xproj<<<dim3(16, 256), 256>>>(h0p, Wih1, bih1, bhh1, xp, 256);
    lstm_kernel<<<128, 512>>>(Whh1, xp, h1p);
    attn_kernel<<<16, 256, ATTN_SMEM_BYTES>>>(h1p, Wq, bq, Wk, bk, Wv, bv, Wo, bo,
                                              Wm, bm, Wvar, bvar, out);
}